// round 12
// baseline (speedup 1.0000x reference)
#include <cuda_runtime.h>
#include <cstdint>

#define T_STEPS 16
#define NB      32
#define HH      32
#define WW      32
#define COUT    128
#define HW      (HH*WW)
#define ELEMS_T (NB*128*HH*WW)
#define IMGS    (T_STEPS*NB)
#define NTILES  (IMGS*8)
#define GRID    152
#define NTHREADS 512

// Bit-packed spikes: word (img, h, c) = 32 px of row h, channel c.
__device__ uint32_t g_spk[(size_t)IMGS * 32 * 128];

// ---------------------------------------------------------------------------
// Kernel 1: LIF scan -> bit-packed spikes.
// v-scan first (no shuffles), then 16 independent shuffle-OR trees.
// ---------------------------------------------------------------------------
__global__ __launch_bounds__(256) void lif_kernel(const float* __restrict__ x)
{
    const int i = (blockIdx.x * 256 + threadIdx.x) * 4;   // px index, w fastest
    if (i >= ELEMS_T) return;
    const int lane = threadIdx.x & 31;
    const int w0   = i & 31;
    const size_t waddr = ((size_t)(i >> 17)) * 4096
                       + (size_t)((i >> 5) & 31) * 128
                       + (size_t)((i >> 10) & 127);
    float4 xv[T_STEPS];
#pragma unroll
    for (int t = 0; t < T_STEPS; t++)
        xv[t] = __ldcs(reinterpret_cast<const float4*>(x + (size_t)t * ELEMS_T + i));

    uint32_t m[T_STEPS];
    float v0 = 0.f, v1 = 0.f, v2 = 0.f, v3 = 0.f;
#pragma unroll
    for (int t = 0; t < T_STEPS; t++) {
        v0 = v0 + (xv[t].x - v0) * 0.5f;
        v1 = v1 + (xv[t].y - v1) * 0.5f;
        v2 = v2 + (xv[t].z - v2) * 0.5f;
        v3 = v3 + (xv[t].w - v3) * 0.5f;
        uint32_t nib = (v0 >= 1.0f ? 1u : 0u) | (v1 >= 1.0f ? 2u : 0u)
                     | (v2 >= 1.0f ? 4u : 0u) | (v3 >= 1.0f ? 8u : 0u);
        if (v0 >= 1.0f) v0 = 0.f;
        if (v1 >= 1.0f) v1 = 0.f;
        if (v2 >= 1.0f) v2 = 0.f;
        if (v3 >= 1.0f) v3 = 0.f;
        m[t] = nib << w0;
    }
    // 16 independent 3-deep shuffle-OR trees (latency overlapped by ILP)
#pragma unroll
    for (int t = 0; t < T_STEPS; t++) {
        uint32_t w = m[t];
        w |= __shfl_xor_sync(0xFFFFFFFFu, w, 1);
        w |= __shfl_xor_sync(0xFFFFFFFFu, w, 2);
        w |= __shfl_xor_sync(0xFFFFFFFFu, w, 4);
        m[t] = w;
    }
    if ((lane & 7) == 0) {
#pragma unroll
        for (int t = 0; t < T_STEPS; t++)
            __stcg(&g_spk[(size_t)t * (NB * 4096) + waddr], m[t]);
    }
}

// ---------------------------------------------------------------------------
// helpers
// ---------------------------------------------------------------------------
typedef unsigned long long u64;
__device__ __forceinline__ uint32_t packh2(float lo, float hi) {
    uint32_t r;
    asm("cvt.rn.f16x2.f32 %0, %1, %2;" : "=r"(r) : "f"(hi), "f"(lo));
    return r;
}
__device__ __forceinline__ u64 pk2(float lo, float hi) {
    u64 r; asm("mov.b64 %0, {%1, %2};" : "=l"(r) : "f"(lo), "f"(hi)); return r;
}
__device__ __forceinline__ u64 pk2u(uint32_t lo, uint32_t hi) {
    u64 r; asm("mov.b64 %0, {%1, %2};" : "=l"(r) : "r"(lo), "r"(hi)); return r;
}
__device__ __forceinline__ void upk2(float& lo, float& hi, u64 v) {
    asm("mov.b64 {%0, %1}, %2;" : "=f"(lo), "=f"(hi) : "l"(v));
}
__device__ __forceinline__ void ffma2(u64& d, u64 a, u64 b) {
    asm("fma.rn.f32x2 %0, %1, %2, %0;" : "+l"(d) : "l"(a), "l"(b));
}
// exact f32x2 pair {bit s, bit s+16} of wd
__device__ __forceinline__ u64 bitpair(uint32_t wd, int s) {
    uint32_t r1 = (wd >> s) & 0x00010001u;
    uint32_t lo = r1 * 0x3F800000u;
    uint32_t hi = (r1 * 0x3F80u) & 0xFFFF0000u;
    return pk2u(lo, hi);
}
__device__ __forceinline__ void mma_f16(float& c0, float& c1, float& c2, float& c3,
                                        uint32_t a0, uint32_t a1, uint32_t a2, uint32_t a3,
                                        uint32_t b0, uint32_t b1)
{
    asm volatile(
        "mma.sync.aligned.m16n8k16.row.col.f32.f16.f16.f32 "
        "{%0,%1,%2,%3}, {%4,%5,%6,%7}, {%8,%9}, {%0,%1,%2,%3};"
        : "+f"(c0), "+f"(c1), "+f"(c2), "+f"(c3)
        : "r"(a0), "r"(a1), "r"(a2), "r"(a3), "r"(b0), "r"(b1));
}
__device__ __forceinline__ void stcs2(float* p, float a, float b) {
    float2 v = make_float2(a, b);
    __stcs(reinterpret_cast<float2*>(p), v);
}
#define BAR_SYNC(id)   asm volatile("bar.sync %0, %1;"   :: "r"(id), "r"(NTHREADS) : "memory")
#define BAR_ARRIVE(id) asm volatile("bar.arrive %0, %1;" :: "r"(id), "r"(NTHREADS) : "memory")

// ---------------------------------------------------------------------------
// SMEM layout (bytes) — round-10 double-buffer configuration
// ---------------------------------------------------------------------------
#define OFF_BIAS  0
#define OFF_DWW   512
#define OFF_A     5120
#define OFF_B0    37888
#define OFF_B1    71680
#define BSTRIDE   132
#define SMEM_TOTAL 105472

// ---------------------------------------------------------------------------
// Kernel 2: warp-specialized fused dw3x3 (producer warps 8-15, FFMA2) +
//           pw1x1+BN GEMM (consumer warps 0-7, mma.sync fp16)
// Double-buffered B. Barriers: full[b]=1+b, empty[b]=3+b.
// ---------------------------------------------------------------------------
__global__ __launch_bounds__(NTHREADS, 1) void fused_ws_kernel(
    const float* __restrict__ dw_w,  const float* __restrict__ dw_b,
    const float* __restrict__ pw_w,  const float* __restrict__ pw_b,
    const float* __restrict__ gamma, const float* __restrict__ beta,
    const float* __restrict__ rmean, const float* __restrict__ rvar,
    float* __restrict__ out)
{
    extern __shared__ unsigned char smem[];
    float*    s_bias = reinterpret_cast<float*>(smem + OFF_BIAS);
    float*    s_dww  = reinterpret_cast<float*>(smem + OFF_DWW);
    uint32_t* s_A    = reinterpret_cast<uint32_t*>(smem + OFF_A);
    uint32_t* sB0    = reinterpret_cast<uint32_t*>(smem + OFF_B0);
    uint32_t* sB1    = reinterpret_cast<uint32_t*>(smem + OFF_B1);

    const int tid = threadIdx.x;
    const int lid = tid & 31;

    // ================= one-time setup =================
    for (int i = tid; i < 1152; i += NTHREADS) s_dww[i] = dw_w[i];
    if (tid < 128) {
        int o = tid;
        float sc = gamma[o] * rsqrtf(rvar[o] + 1e-5f);
        float s = 0.f;
        for (int c = 0; c < 128; c++) s += pw_w[o * 128 + c] * dw_b[c];
        s_bias[o] = beta[o] + sc * (pw_b[o] - rmean[o] + s);
    }
    for (int i = tid; i < 2048; i += NTHREADS) {
        int seg  = i >> 5, lane = i & 31;
        int smg  = seg >> 4, smt = (seg >> 3) & 1, sks = seg & 7;
        int sg   = lane >> 2, st4 = lane & 3;
        int o0   = smg * 32 + smt * 16 + sg;
        int o1   = o0 + 8;
        float s0 = gamma[o0] * rsqrtf(rvar[o0] + 1e-5f);
        float s1 = gamma[o1] * rsqrtf(rvar[o1] + 1e-5f);
        const float* w0 = pw_w + o0 * 128;
        const float* w1 = pw_w + o1 * 128;
        int cl = sks * 8 + st4;
        uint4 v;
        v.x = packh2(w0[cl]     * s0, w0[cl + 64] * s0);
        v.y = packh2(w1[cl]     * s1, w1[cl + 64] * s1);
        v.z = packh2(w0[cl + 4] * s0, w0[cl + 68] * s0);
        v.w = packh2(w1[cl + 4] * s1, w1[cl + 68] * s1);
        *reinterpret_cast<uint4*>(s_A + (size_t)i * 4) = v;
    }
    __syncthreads();

    const int t0 = blockIdx.x;

    if (tid < 256) {
        // =====================================================================
        // CONSUMER: GEMM + epilogue (warps 0-7)
        // =====================================================================
        const int wid = tid >> 5;
        const int g   = lid >> 2;
        const int t4  = lid & 3;
        const int mg  = wid & 3;
        const int ng  = wid >> 2;
        const int ob  = mg * 32;
        const int nb  = ng * 64;

        const uint32_t* bld0 = sB0 + t4 * BSTRIDE + g * 16 + ng * 8;
        const uint32_t* bld1 = sB1 + t4 * BSTRIDE + g * 16 + ng * 8;
        const uint32_t* ald  = s_A + (size_t)(mg * 16) * 128 + (size_t)lid * 4;

        const float bias00 = s_bias[ob + g];
        const float bias01 = s_bias[ob + g + 8];
        const float bias10 = s_bias[ob + 16 + g];
        const float bias11 = s_bias[ob + 24 + g];

        int it = 0;
        for (int t = t0; t < NTILES; t += GRID, ++it) {
            const int b = it & 1;
            BAR_SYNC(1 + b);                      // wait B[b] full

            float acc[2][8][4];
#pragma unroll
            for (int mt = 0; mt < 2; mt++)
#pragma unroll
                for (int nt = 0; nt < 8; nt++)
#pragma unroll
                    for (int r = 0; r < 4; r++) acc[mt][nt][r] = 0.f;

            const uint32_t* bld = b ? bld1 : bld0;
#pragma unroll
            for (int s = 0; s < 8; s++) {
                const uint32_t* bp = bld + (8 * s) * BSTRIDE;
                uint4 u0 = *reinterpret_cast<const uint4*>(bp);
                uint4 u1 = *reinterpret_cast<const uint4*>(bp + 4);
                uint4 u2 = *reinterpret_cast<const uint4*>(bp + 4 * BSTRIDE);
                uint4 u3 = *reinterpret_cast<const uint4*>(bp + 4 * BSTRIDE + 4);
                uint4 a0 = *reinterpret_cast<const uint4*>(ald + (size_t)s * 128);
                uint4 a1 = *reinterpret_cast<const uint4*>(ald + (size_t)(s + 8) * 128);
                uint32_t b0[8] = {u0.x, u0.y, u0.z, u0.w, u1.x, u1.y, u1.z, u1.w};
                uint32_t b1[8] = {u2.x, u2.y, u2.z, u2.w, u3.x, u3.y, u3.z, u3.w};
#pragma unroll
                for (int nt = 0; nt < 8; nt++) {
                    mma_f16(acc[0][nt][0], acc[0][nt][1], acc[0][nt][2], acc[0][nt][3],
                            a0.x, a0.y, a0.z, a0.w, b0[nt], b1[nt]);
                    mma_f16(acc[1][nt][0], acc[1][nt][1], acc[1][nt][2], acc[1][nt][3],
                            a1.x, a1.y, a1.z, a1.w, b0[nt], b1[nt]);
                }
            }
            BAR_ARRIVE(3 + b);                    // release B[b] BEFORE stores

            // epilogue (overlaps producer's next dw)
            {
                const int img = t >> 3, ptile = t & 7;
                float* obase = out + (size_t)img * (COUT * HW) + ptile * 128 + nb + 2 * t4;
#pragma unroll
                for (int mt = 0; mt < 2; mt++) {
                    const float blo = (mt == 0) ? bias00 : bias10;
                    const float bhi = (mt == 0) ? bias01 : bias11;
                    float* r0 = obase + (size_t)(ob + mt * 16 + g) * HW;
#pragma unroll
                    for (int nt = 0; nt < 8; nt++) {
                        stcs2(r0 + nt * 8,          acc[mt][nt][0] + blo, acc[mt][nt][1] + blo);
                        stcs2(r0 + 8 * HW + nt * 8, acc[mt][nt][2] + bhi, acc[mt][nt][3] + bhi);
                    }
                }
            }
        }
    } else {
        // =====================================================================
        // PRODUCER: depthwise 3x3 via packed f32x2 FFMA (warps 8-15)
        // =====================================================================
        const int local = tid - 256;
        const int cp    = local & 63;
        const int row   = local >> 6;

        float w0r[9], w1r[9];
#pragma unroll
        for (int i = 0; i < 9; i++) {
            w0r[i] = s_dww[cp * 9 + i];
            w1r[i] = s_dww[(cp + 64) * 9 + i];
        }
        uint32_t* bst0 = sB0 + cp * BSTRIDE + row * 4;
        uint32_t* bst1 = sB1 + cp * BSTRIDE + row * 4;

        auto ldspk = [&](int t, uint32_t (&sw)[6]) {
            const int img = t >> 3, r0 = (t & 7) * 4;
            const uint32_t* gg = g_spk + (size_t)img * 4096;
#pragma unroll
            for (int rr = 0; rr < 3; rr++) {
                int gr = r0 - 1 + row + rr;
                bool ok = (unsigned)gr < 32u;
                sw[rr]     = ok ? gg[gr * 128 + cp]      : 0u;
                sw[rr + 3] = ok ? gg[gr * 128 + cp + 64] : 0u;
            }
        };
        auto dwcomp = [&](const uint32_t (&sw)[6], uint32_t* bst) {
            u64 O0[16], O1[16];
#pragma unroll
            for (int i = 0; i < 16; i++) { O0[i] = 0ull; O1[i] = 0ull; }
#pragma unroll
            for (int h = 0; h < 2; h++) {
                const float* w = h ? w1r : w0r;
                u64* O = h ? O1 : O0;
#pragma unroll
                for (int rr = 0; rr < 3; rr++) {
                    const uint32_t wd = sw[h * 3 + rr];
                    const u64 wa2 = pk2(w[rr * 3],     w[rr * 3]);
                    const u64 wb2 = pk2(w[rr * 3 + 1], w[rr * 3 + 1]);
                    const u64 wc2 = pk2(w[rr * 3 + 2], w[rr * 3 + 2]);
                    u64 Pm = pk2u(0u, ((wd >> 15) & 1u) * 0x3F800000u);
                    u64 Pc = bitpair(wd, 0);
#pragma unroll
                    for (int k = 0; k < 16; k++) {
                        u64 Pn = (k < 15) ? bitpair(wd, k + 1)
                                          : pk2u(((wd >> 16) & 1u) * 0x3F800000u, 0u);
                        ffma2(O[k], wa2, Pm);
                        ffma2(O[k], wb2, Pc);
                        ffma2(O[k], wc2, Pn);
                        Pm = Pc; Pc = Pn;
                    }
                }
            }
#pragma unroll
            for (int j = 0; j < 8; j++) {
                float a0, a16, a8, a24, c0, c16, c8, c24;
                upk2(a0, a16, O0[j]);
                upk2(a8, a24, O0[j + 8]);
                upk2(c0, c16, O1[j]);
                upk2(c8, c24, O1[j + 8]);
                uint4 v;
                v.x = packh2(a0,  c0);
                v.y = packh2(a8,  c8);
                v.z = packh2(a16, c16);
                v.w = packh2(a24, c24);
                *reinterpret_cast<uint4*>(bst + j * 16) = v;
            }
        };

        uint32_t sw[6];
        ldspk(t0, sw);

        int it = 0;
        for (int t = t0; t < NTILES; t += GRID, ++it) {
            const int b = it & 1;
            if (it >= 2) BAR_SYNC(3 + b);         // wait B[b] empty
            dwcomp(sw, b ? bst1 : bst0);
            BAR_ARRIVE(1 + b);                    // signal B[b] full
            if (t + GRID < NTILES) ldspk(t + GRID, sw);
        }
    }
}

// ---------------------------------------------------------------------------
// Launcher
// ---------------------------------------------------------------------------
extern "C" void kernel_launch(void* const* d_in, const int* in_sizes, int n_in,
                              void* d_out, int out_size)
{
    const float* x     = (const float*)d_in[0];
    const float* dw_w  = (const float*)d_in[1];
    const float* dw_b  = (const float*)d_in[2];
    const float* pw_w  = (const float*)d_in[3];
    const float* pw_b  = (const float*)d_in[4];
    const float* gamma = (const float*)d_in[5];
    const float* beta  = (const float*)d_in[6];
    const float* rmean = (const float*)d_in[7];
    const float* rvar  = (const float*)d_in[8];
    float* out = (float*)d_out;

    lif_kernel<<<ELEMS_T / (256 * 4), 256>>>(x);

    cudaFuncSetAttribute(fused_ws_kernel,
                         cudaFuncAttributeMaxDynamicSharedMemorySize, SMEM_TOTAL);
    fused_ws_kernel<<<GRID, NTHREADS, SMEM_TOTAL>>>(dw_w, dw_b, pw_w, pw_b,
                                                    gamma, beta, rmean, rvar, out);
}

// round 13
// speedup vs baseline: 1.0794x; 1.0794x over previous
#include <cuda_runtime.h>
#include <cstdint>

#define T_STEPS 16
#define NB      32
#define HH      32
#define WW      32
#define COUT    128
#define HW      (HH*WW)
#define ELEMS_T (NB*128*HH*WW)
#define IMGS    (T_STEPS*NB)
#define NTILES  (IMGS*8)
#define GRID    152
#define NTHREADS 512

// Bit-packed spikes: word (img, h, c) = 32 px of row h, channel c.
__device__ uint32_t g_spk[(size_t)IMGS * 32 * 128];

// ---------------------------------------------------------------------------
// Kernel 1: LIF scan -> bit-packed spikes
// ---------------------------------------------------------------------------
__global__ __launch_bounds__(256) void lif_kernel(const float* __restrict__ x)
{
    const int i = (blockIdx.x * 256 + threadIdx.x) * 4;
    if (i >= ELEMS_T) return;
    const int lane = threadIdx.x & 31;
    const int w0   = i & 31;
    const size_t waddr = ((size_t)(i >> 17)) * 4096
                       + (size_t)((i >> 5) & 31) * 128
                       + (size_t)((i >> 10) & 127);
    float4 xv[T_STEPS];
#pragma unroll
    for (int t = 0; t < T_STEPS; t++)
        xv[t] = __ldcs(reinterpret_cast<const float4*>(x + (size_t)t * ELEMS_T + i));

    uint32_t m[T_STEPS];
    float v0 = 0.f, v1 = 0.f, v2 = 0.f, v3 = 0.f;
#pragma unroll
    for (int t = 0; t < T_STEPS; t++) {
        v0 = v0 + (xv[t].x - v0) * 0.5f;
        v1 = v1 + (xv[t].y - v1) * 0.5f;
        v2 = v2 + (xv[t].z - v2) * 0.5f;
        v3 = v3 + (xv[t].w - v3) * 0.5f;
        uint32_t nib = (v0 >= 1.0f ? 1u : 0u) | (v1 >= 1.0f ? 2u : 0u)
                     | (v2 >= 1.0f ? 4u : 0u) | (v3 >= 1.0f ? 8u : 0u);
        if (v0 >= 1.0f) v0 = 0.f;
        if (v1 >= 1.0f) v1 = 0.f;
        if (v2 >= 1.0f) v2 = 0.f;
        if (v3 >= 1.0f) v3 = 0.f;
        m[t] = nib << w0;
    }
#pragma unroll
    for (int t = 0; t < T_STEPS; t++) {
        uint32_t w = m[t];
        w |= __shfl_xor_sync(0xFFFFFFFFu, w, 1);
        w |= __shfl_xor_sync(0xFFFFFFFFu, w, 2);
        w |= __shfl_xor_sync(0xFFFFFFFFu, w, 4);
        m[t] = w;
    }
    if ((lane & 7) == 0) {
#pragma unroll
        for (int t = 0; t < T_STEPS; t++)
            __stcg(&g_spk[(size_t)t * (NB * 4096) + waddr], m[t]);
    }
}

// ---------------------------------------------------------------------------
// helpers
// ---------------------------------------------------------------------------
__device__ __forceinline__ uint32_t packh2(float lo, float hi) {
    uint32_t r;
    asm("cvt.rn.f16x2.f32 %0, %1, %2;" : "=r"(r) : "f"(hi), "f"(lo));
    return r;
}
__device__ __forceinline__ uint32_t h2bcast(float f) {
    uint32_t r;
    asm("{\n\t.reg .b16 h;\n\tcvt.rn.f16.f32 h, %1;\n\tmov.b32 %0, {h, h};\n\t}"
        : "=r"(r) : "f"(f));
    return r;
}
__device__ __forceinline__ void hfma2(uint32_t& d, uint32_t a, uint32_t b) {
    asm("fma.rn.f16x2 %0, %1, %2, %0;" : "+r"(d) : "r"(a), "r"(b));
}
__device__ __forceinline__ void mma_f16(float& c0, float& c1, float& c2, float& c3,
                                        uint32_t a0, uint32_t a1, uint32_t a2, uint32_t a3,
                                        uint32_t b0, uint32_t b1)
{
    asm volatile(
        "mma.sync.aligned.m16n8k16.row.col.f32.f16.f16.f32 "
        "{%0,%1,%2,%3}, {%4,%5,%6,%7}, {%8,%9}, {%0,%1,%2,%3};"
        : "+f"(c0), "+f"(c1), "+f"(c2), "+f"(c3)
        : "r"(a0), "r"(a1), "r"(a2), "r"(a3), "r"(b0), "r"(b1));
}
__device__ __forceinline__ void stcs2(float* p, float a, float b) {
    float2 v = make_float2(a, b);
    __stcs(reinterpret_cast<float2*>(p), v);
}
#define BAR_SYNC(id)   asm volatile("bar.sync %0, %1;"   :: "r"(id), "r"(NTHREADS) : "memory")
#define BAR_ARRIVE(id) asm volatile("bar.arrive %0, %1;" :: "r"(id), "r"(NTHREADS) : "memory")

// ---------------------------------------------------------------------------
// SMEM layout (bytes). Each B buffer holds TWO tiles (2 x 33792 B).
// ---------------------------------------------------------------------------
#define OFF_BIAS  0
#define OFF_DWW   512
#define OFF_A     5120
#define OFF_B0    37888
#define BSUB      33792                  // one tile = 64 kw x 132-word stride
#define OFF_B1    (OFF_B0 + 2*BSUB)      // 105472
#define BSTRIDE   132
#define BSUBW     (BSUB/4)               // 8448 words
#define SMEM_TOTAL (OFF_B1 + 2*BSUB)     // 173056

// ---------------------------------------------------------------------------
// Kernel 2: warp-specialized fused dw3x3 (producer warps 8-15, f16x2 HFMA2) +
//           pw1x1+BN GEMM (consumer warps 0-7, mma.sync fp16)
// Double-buffered, 2 tiles per barrier phase.
// Barriers: full[b]=1+b, empty[b]=3+b.
// ---------------------------------------------------------------------------
__global__ __launch_bounds__(NTHREADS, 1) void fused_ws_kernel(
    const float* __restrict__ dw_w,  const float* __restrict__ dw_b,
    const float* __restrict__ pw_w,  const float* __restrict__ pw_b,
    const float* __restrict__ gamma, const float* __restrict__ beta,
    const float* __restrict__ rmean, const float* __restrict__ rvar,
    float* __restrict__ out)
{
    extern __shared__ unsigned char smem[];
    float*    s_bias = reinterpret_cast<float*>(smem + OFF_BIAS);
    float*    s_dww  = reinterpret_cast<float*>(smem + OFF_DWW);
    uint32_t* s_A    = reinterpret_cast<uint32_t*>(smem + OFF_A);
    uint32_t* sB0    = reinterpret_cast<uint32_t*>(smem + OFF_B0);
    uint32_t* sB1    = reinterpret_cast<uint32_t*>(smem + OFF_B1);

    const int tid = threadIdx.x;
    const int lid = tid & 31;

    // ================= one-time setup =================
    for (int i = tid; i < 1152; i += NTHREADS) s_dww[i] = dw_w[i];
    if (tid < 128) {
        int o = tid;
        float sc = gamma[o] * rsqrtf(rvar[o] + 1e-5f);
        float s = 0.f;
        for (int c = 0; c < 128; c++) s += pw_w[o * 128 + c] * dw_b[c];
        s_bias[o] = beta[o] + sc * (pw_b[o] - rmean[o] + s);
    }
    for (int i = tid; i < 2048; i += NTHREADS) {
        int seg  = i >> 5, lane = i & 31;
        int smg  = seg >> 4, smt = (seg >> 3) & 1, sks = seg & 7;
        int sg   = lane >> 2, st4 = lane & 3;
        int o0   = smg * 32 + smt * 16 + sg;
        int o1   = o0 + 8;
        float s0 = gamma[o0] * rsqrtf(rvar[o0] + 1e-5f);
        float s1 = gamma[o1] * rsqrtf(rvar[o1] + 1e-5f);
        const float* w0 = pw_w + o0 * 128;
        const float* w1 = pw_w + o1 * 128;
        int cl = sks * 8 + st4;
        uint4 v;
        v.x = packh2(w0[cl]     * s0, w0[cl + 64] * s0);
        v.y = packh2(w1[cl]     * s1, w1[cl + 64] * s1);
        v.z = packh2(w0[cl + 4] * s0, w0[cl + 68] * s0);
        v.w = packh2(w1[cl + 4] * s1, w1[cl + 68] * s1);
        *reinterpret_cast<uint4*>(s_A + (size_t)i * 4) = v;
    }
    __syncthreads();

    const int t0 = blockIdx.x;

    if (tid < 256) {
        // =====================================================================
        // CONSUMER: GEMM + epilogue (warps 0-7)
        // =====================================================================
        const int wid = tid >> 5;
        const int g   = lid >> 2;
        const int t4  = lid & 3;
        const int mg  = wid & 3;
        const int ng  = wid >> 2;
        const int ob  = mg * 32;
        const int nb  = ng * 64;

        const uint32_t* bldp[2] = { sB0 + t4 * BSTRIDE + g * 16 + ng * 8,
                                    sB1 + t4 * BSTRIDE + g * 16 + ng * 8 };
        const uint32_t* ald  = s_A + (size_t)(mg * 16) * 128 + (size_t)lid * 4;

        const float bias00 = s_bias[ob + g];
        const float bias01 = s_bias[ob + g + 8];
        const float bias10 = s_bias[ob + 16 + g];
        const float bias11 = s_bias[ob + 24 + g];

        float acc[2][8][4];

        auto gemm = [&](const uint32_t* bld) {
#pragma unroll
            for (int mt = 0; mt < 2; mt++)
#pragma unroll
                for (int nt = 0; nt < 8; nt++)
#pragma unroll
                    for (int r = 0; r < 4; r++) acc[mt][nt][r] = 0.f;
#pragma unroll
            for (int s = 0; s < 8; s++) {
                const uint32_t* bp = bld + (8 * s) * BSTRIDE;
                uint4 u0 = *reinterpret_cast<const uint4*>(bp);
                uint4 u1 = *reinterpret_cast<const uint4*>(bp + 4);
                uint4 u2 = *reinterpret_cast<const uint4*>(bp + 4 * BSTRIDE);
                uint4 u3 = *reinterpret_cast<const uint4*>(bp + 4 * BSTRIDE + 4);
                uint4 a0 = *reinterpret_cast<const uint4*>(ald + (size_t)s * 128);
                uint4 a1 = *reinterpret_cast<const uint4*>(ald + (size_t)(s + 8) * 128);
                uint32_t b0[8] = {u0.x, u0.y, u0.z, u0.w, u1.x, u1.y, u1.z, u1.w};
                uint32_t b1[8] = {u2.x, u2.y, u2.z, u2.w, u3.x, u3.y, u3.z, u3.w};
#pragma unroll
                for (int nt = 0; nt < 8; nt++) {
                    mma_f16(acc[0][nt][0], acc[0][nt][1], acc[0][nt][2], acc[0][nt][3],
                            a0.x, a0.y, a0.z, a0.w, b0[nt], b1[nt]);
                    mma_f16(acc[1][nt][0], acc[1][nt][1], acc[1][nt][2], acc[1][nt][3],
                            a1.x, a1.y, a1.z, a1.w, b0[nt], b1[nt]);
                }
            }
        };
        auto epilogue = [&](int t) {
            const int img = t >> 3, ptile = t & 7;
            float* obase = out + (size_t)img * (COUT * HW) + ptile * 128 + nb + 2 * t4;
#pragma unroll
            for (int mt = 0; mt < 2; mt++) {
                const float blo = (mt == 0) ? bias00 : bias10;
                const float bhi = (mt == 0) ? bias01 : bias11;
                float* r0 = obase + (size_t)(ob + mt * 16 + g) * HW;
#pragma unroll
                for (int nt = 0; nt < 8; nt++) {
                    stcs2(r0 + nt * 8,          acc[mt][nt][0] + blo, acc[mt][nt][1] + blo);
                    stcs2(r0 + 8 * HW + nt * 8, acc[mt][nt][2] + bhi, acc[mt][nt][3] + bhi);
                }
            }
        };

        int it = 0;
        for (int t = t0; t < NTILES; t += 2 * GRID, ++it) {
            const int b = it & 1;
            const int t1 = t + GRID;
            const bool have1 = (t1 < NTILES);
            BAR_SYNC(1 + b);                      // wait phase full
            gemm(bldp[b]);
            if (!have1) BAR_ARRIVE(3 + b);        // release if sub1 absent
            epilogue(t);
            if (have1) {
                gemm(bldp[b] + BSUBW);
                BAR_ARRIVE(3 + b);                // release after last read
                epilogue(t1);
            }
        }
    } else {
        // =====================================================================
        // PRODUCER: depthwise 3x3 in f16x2 HFMA2 (warps 8-15)
        // operand pair (px s, px s+16) = ((wd>>s)&0x00010001)*0x3C00
        // =====================================================================
        const int local = tid - 256;
        const int cp    = local & 63;
        const int row   = local >> 6;

        uint32_t w0h[9], w1h[9];
#pragma unroll
        for (int i = 0; i < 9; i++) {
            w0h[i] = h2bcast(s_dww[cp * 9 + i]);
            w1h[i] = h2bcast(s_dww[(cp + 64) * 9 + i]);
        }
        uint32_t* bstp[2] = { sB0 + cp * BSTRIDE + row * 4,
                              sB1 + cp * BSTRIDE + row * 4 };

        auto ldspk = [&](int t, uint32_t (&sw)[6]) {
            const int img = t >> 3, r0 = (t & 7) * 4;
            const uint32_t* gg = g_spk + (size_t)img * 4096;
#pragma unroll
            for (int rr = 0; rr < 3; rr++) {
                int gr = r0 - 1 + row + rr;
                bool ok = (unsigned)gr < 32u;
                sw[rr]     = ok ? gg[gr * 128 + cp]      : 0u;
                sw[rr + 3] = ok ? gg[gr * 128 + cp + 64] : 0u;
            }
        };
        auto dwcomp = [&](const uint32_t (&sw)[6], uint32_t* bst) {
            uint32_t O0[16], O1[16];
#pragma unroll
            for (int i = 0; i < 16; i++) { O0[i] = 0u; O1[i] = 0u; }
#pragma unroll
            for (int h = 0; h < 2; h++) {
                const uint32_t* wh = h ? w1h : w0h;
                uint32_t* O = h ? O1 : O0;
#pragma unroll
                for (int rr = 0; rr < 3; rr++) {
                    const uint32_t wd = sw[h * 3 + rr];
                    const uint32_t wa = wh[rr * 3], wb = wh[rr * 3 + 1], wc = wh[rr * 3 + 2];
                    uint32_t Pm = ((wd >> 15) & 1u) * 0x3C000000u;       // (0, bit15)
                    uint32_t Pc = (wd & 0x00010001u) * 0x3C00u;          // (bit0, bit16)
#pragma unroll
                    for (int k = 0; k < 16; k++) {
                        uint32_t Pn = (k < 15)
                            ? ((wd >> (k + 1)) & 0x00010001u) * 0x3C00u
                            : ((wd >> 16) & 1u) * 0x3C00u;               // (bit16, 0)
                        hfma2(O[k], wa, Pm);
                        hfma2(O[k], wb, Pc);
                        hfma2(O[k], wc, Pn);
                        Pm = Pc; Pc = Pn;
                    }
                }
            }
            // repack: word for px k = (lo16 O0[k], lo16 O1[k]); px k+16 = hi halves
#pragma unroll
            for (int j = 0; j < 8; j++) {
                uint4 v;
                v.x = __byte_perm(O0[j],     O1[j],     0x5410u);
                v.y = __byte_perm(O0[j + 8], O1[j + 8], 0x5410u);
                v.z = __byte_perm(O0[j],     O1[j],     0x7632u);
                v.w = __byte_perm(O0[j + 8], O1[j + 8], 0x7632u);
                *reinterpret_cast<uint4*>(bst + j * 16) = v;
            }
        };

        uint32_t swA[6], swB[6];
        ldspk(t0, swA);
        if (t0 + GRID < NTILES) ldspk(t0 + GRID, swB);

        int it = 0;
        for (int t = t0; t < NTILES; t += 2 * GRID, ++it) {
            const int b = it & 1;
            if (it >= 2) BAR_SYNC(3 + b);         // wait phase empty
            dwcomp(swA, bstp[b]);
            if (t + GRID < NTILES) dwcomp(swB, bstp[b] + BSUBW);
            BAR_ARRIVE(1 + b);                    // signal phase full
            const int tn = t + 2 * GRID;
            if (tn < NTILES)        ldspk(tn, swA);
            if (tn + GRID < NTILES) ldspk(tn + GRID, swB);
        }
    }
}

// ---------------------------------------------------------------------------
// Launcher
// ---------------------------------------------------------------------------
extern "C" void kernel_launch(void* const* d_in, const int* in_sizes, int n_in,
                              void* d_out, int out_size)
{
    const float* x     = (const float*)d_in[0];
    const float* dw_w  = (const float*)d_in[1];
    const float* dw_b  = (const float*)d_in[2];
    const float* pw_w  = (const float*)d_in[3];
    const float* pw_b  = (const float*)d_in[4];
    const float* gamma = (const float*)d_in[5];
    const float* beta  = (const float*)d_in[6];
    const float* rmean = (const float*)d_in[7];
    const float* rvar  = (const float*)d_in[8];
    float* out = (float*)d_out;

    lif_kernel<<<ELEMS_T / (256 * 4), 256>>>(x);

    cudaFuncSetAttribute(fused_ws_kernel,
                         cudaFuncAttributeMaxDynamicSharedMemorySize, SMEM_TOTAL);
    fused_ws_kernel<<<GRID, NTHREADS, SMEM_TOTAL>>>(dw_w, dw_b, pw_w, pw_b,
                                                    gamma, beta, rmean, rvar, out);
}